// round 14
// baseline (speedup 1.0000x reference)
#include <cuda_runtime.h>
#include <cuda_bf16.h>
#include <cuda_fp16.h>
#include <math.h>
#include <stdint.h>

#define N_TOK   4096
#define DIM     1024
#define HEADS   16
#define HD      64
#define QKV_N   3072
#define KW      (DIM / 2)

#define QSCALE  0.180336880111120429f

// ---------------------------------------------------------------------------
// Scratch
// ---------------------------------------------------------------------------
__device__ float    g_qkv[N_TOK * QKV_N];
__device__ float    g_h2[N_TOK * DIM];
__device__ float4   g_trig[N_TOK * 32];
__device__ uint32_t g_XP[N_TOK * KW];
__device__ uint32_t g_QP[N_TOK * KW];
__device__ uint32_t g_KP[N_TOK * KW];
__device__ uint32_t g_VP[HEADS * 64 * 2048];
__device__ uint32_t g_AtP[N_TOK * KW];
__device__ uint32_t g_H1P[N_TOK * KW];
__device__ uint32_t g_WqkvP[QKV_N * KW];
__device__ uint32_t g_Wo1P[DIM * KW];
__device__ uint32_t g_Wo2P[DIM * KW];

// ---------------------------------------------------------------------------
// helpers
// ---------------------------------------------------------------------------
__device__ __forceinline__ uint32_t pack2h(float lo, float hi) {
    uint32_t r;
    asm("cvt.rn.f16x2.f32 %0, %1, %2;" : "=r"(r) : "f"(hi), "f"(lo));
    return r;
}
__device__ __forceinline__ float ex2f(float x) {
    float r;
    asm("ex2.approx.f32 %0, %1;" : "=f"(r) : "f"(x));
    return r;
}
__device__ __forceinline__ uint32_t ex2h2(uint32_t x) {
    uint32_t r;
    asm("ex2.approx.f16x2 %0, %1;" : "=r"(r) : "r"(x));
    return r;
}
__device__ __forceinline__ void mma_fp16(float* c, const uint32_t* a, const uint32_t* b) {
    asm volatile("mma.sync.aligned.m16n8k16.row.col.f32.f16.f16.f32 "
        "{%0,%1,%2,%3}, {%4,%5,%6,%7}, {%8,%9}, {%0,%1,%2,%3};"
        : "+f"(c[0]), "+f"(c[1]), "+f"(c[2]), "+f"(c[3])
        : "r"(a[0]), "r"(a[1]), "r"(a[2]), "r"(a[3]), "r"(b[0]), "r"(b[1]));
}
__device__ __forceinline__ void ldsm4(uint32_t* r, uint32_t addr) {
    asm volatile("ldmatrix.sync.aligned.m8n8.x4.shared.b16 {%0,%1,%2,%3}, [%4];"
        : "=r"(r[0]), "=r"(r[1]), "=r"(r[2]), "=r"(r[3]) : "r"(addr));
}
__device__ __forceinline__ uint32_t smem_u32(const void* p) {
    uint32_t a;
    asm("{ .reg .u64 t; cvta.to.shared.u64 t, %1; cvt.u32.u64 %0, t; }"
        : "=r"(a) : "l"(p));
    return a;
}
#define CP_ASYNC16(dst, src) \
    asm volatile("cp.async.cg.shared.global [%0], [%1], 16;" :: "r"(dst), "l"(src))
#define CP_COMMIT() asm volatile("cp.async.commit_group;")
#define CP_WAIT0()  asm volatile("cp.async.wait_group 0;")
#define CP_WAIT1()  asm volatile("cp.async.wait_group 1;")

// ---------------------------------------------------------------------------
// Prep kernels
// ---------------------------------------------------------------------------
__global__ void split_x_kernel(const float* __restrict__ x) {
    int idx = blockIdx.x * 256 + threadIdx.x;
    float2 v = *(const float2*)&x[(size_t)idx * 2];
    g_XP[idx] = pack2h(v.x, v.y);
}

__global__ void trig_kernel() {
    int idx = blockIdx.x * 256 + threadIdx.x;
    int row = idx >> 5;
    int w   = idx & 31;
    int d0  = w * 2;
    int i0  = d0 & 31;

    float invf0 = powf(10000.f, -(float)i0 * (1.f / 32.f));
    float invf1 = powf(10000.f, -(float)(i0 + 1) * (1.f / 32.f));
    float4 r;
    sincosf((float)row * invf0, &r.x, &r.y);
    sincosf((float)row * invf1, &r.z, &r.w);
    g_trig[idx] = r;
}

__global__ void split_w_kernel(const float* __restrict__ W0,
                               const float* __restrict__ W1,
                               const float* __restrict__ W2,
                               int zbase) {
    const int z = zbase + blockIdx.z;
    const float* W;
    uint32_t* P;
    int N;
    if (z == 0)      { W = W0; P = g_WqkvP; N = QKV_N; }
    else if (z == 1) { W = W1; P = g_Wo1P;  N = DIM; }
    else             { W = W2; P = g_Wo2P;  N = DIM; }
    const int n0 = blockIdx.x * 64;
    if (n0 >= N) return;
    const int k0 = blockIdx.y * 64;

    __shared__ float S[64][68];
    const int t = threadIdx.x;
#pragma unroll
    for (int i = 0; i < 4; i++) {
        int slot = i * 256 + t;
        int k = slot >> 4, n4 = (slot & 15) << 2;
        *(float4*)&S[k][n4] = *(const float4*)&W[(size_t)(k0 + k) * N + n0 + n4];
    }
    __syncthreads();
#pragma unroll
    for (int i = 0; i < 8; i++) {
        int slot = i * 256 + t;
        int n = slot >> 5, kwl = slot & 31;
        P[(size_t)(n0 + n) * KW + (k0 >> 1) + kwl] = pack2h(S[2 * kwl][n], S[2 * kwl + 1][n]);
    }
}

__global__ void rope_v_kernel() {
    __shared__ float S[64][68];
    const int t = threadIdx.x;
    const int kt = blockIdx.x, h = blockIdx.y;

#pragma unroll
    for (int i = 0; i < 4; i++) {
        int slot = i * 256 + t;
        int r = slot >> 4, c4 = (slot & 15) << 2;
        *(float4*)&S[r][c4] =
            *(const float4*)&g_qkv[(size_t)(kt * 64 + r) * QKV_N + 2 * DIM + h * HD + c4];
    }
    __syncthreads();
    size_t tb = ((size_t)(h * 64 + kt)) << 11;
#pragma unroll
    for (int i = 0; i < 8; i++) {
        int slot = i * 256 + t;
        int d = slot >> 5, p = slot & 31;
        g_VP[tb + slot] = pack2h(S[2 * p][d], S[2 * p + 1][d]);
    }

#pragma unroll
    for (int i = 0; i < 8; i++) {
        int slot = i * 256 + t;
        int r = slot >> 5, w = slot & 31;
        int row = kt * 64 + r;
        int d0 = w * 2;

        float4 tr = g_trig[row * 32 + w];
        float s0 = tr.x, c0 = tr.y, s1 = tr.z, c1 = tr.w;

        bool half = (d0 < 32);
        size_t base = (size_t)row * QKV_N + h * HD + d0;
        size_t pb   = half ? base + 32 : base - 32;

        float q0 = g_qkv[base],       q1 = g_qkv[base + 1];
        float qp0 = g_qkv[pb],        qp1 = g_qkv[pb + 1];
        float k0 = g_qkv[base + DIM], k1 = g_qkv[base + DIM + 1];
        float kp0 = g_qkv[pb + DIM],  kp1 = g_qkv[pb + DIM + 1];

        float oq0, oq1, ok0, ok1;
        if (half) {
            oq0 = q0 * c0 - qp0 * s0;  oq1 = q1 * c1 - qp1 * s1;
            ok0 = k0 * c0 - kp0 * s0;  ok1 = k1 * c1 - kp1 * s1;
        } else {
            oq0 = q0 * c0 + qp0 * s0;  oq1 = q1 * c1 + qp1 * s1;
            ok0 = k0 * c0 + kp0 * s0;  ok1 = k1 * c1 + kp1 * s1;
        }
        oq0 *= QSCALE; oq1 *= QSCALE;

        size_t widx = (size_t)row * KW + h * 32 + w;
        g_QP[widx] = pack2h(oq0, oq1);
        g_KP[widx] = pack2h(ok0, ok1);
    }
}

// ---------------------------------------------------------------------------
// GEMM: single fp16 A x single fp16 B, BK=64, 2-stage cp.async.
// bm0 = row offset (for row-sliced launches).
// ---------------------------------------------------------------------------
#define GS2 36
#define GEMM_BUF_W (2 * 128 * GS2)
#define GEMM_SMEM  (2 * GEMM_BUF_W * 4)

template <int MODE>
__global__ void __launch_bounds__(512)
gemm_pre(const uint32_t* __restrict__ AP, const uint32_t* __restrict__ BP,
         float* __restrict__ Cf, uint32_t* __restrict__ CP,
         int M, int N, int K, int bm0) {
    extern __shared__ uint32_t sw[];
    const int kw = K >> 1;
    const int t = threadIdx.x;
    const int lane = t & 31;
    const int wid = t >> 5;
    const int wm = wid & 3;
    const int wn = wid >> 2;
    const int bm = bm0 + blockIdx.y * 128;
    const int bn = blockIdx.x * 128;
    const uint32_t sb = smem_u32(sw);

    const int frow = t >> 2;
    const int fw0  = (t & 3) << 3;
    const uint32_t* sAP = &AP[(size_t)(bm + frow) * kw + fw0];
    const uint32_t* sBP = &BP[(size_t)(bn + frow) * kw + fw0];
    const uint32_t dbase = sb + (frow * GS2 + fw0) * 4;

    auto issue = [&](int c, int b) {
        uint32_t d = dbase + (b * GEMM_BUF_W) * 4;
        int go = c * 32;
        CP_ASYNC16(d,                  sAP + go);
        CP_ASYNC16(d + 16,             sAP + go + 4);
        CP_ASYNC16(d + 4608 * 4,       sBP + go);
        CP_ASYNC16(d + 4608 * 4 + 16,  sBP + go + 4);
    };

    const uint32_t aw = ((wm * 32 + (lane & 15)) * GS2 + (lane >> 4) * 4) * 4;
    const int g = lane >> 3;
    const uint32_t bw = ((wn * 32 + (g >> 1) * 8 + (lane & 7)) * GS2 + (g & 1) * 4) * 4;

    float acc[2][4][4];
#pragma unroll
    for (int i = 0; i < 2; i++)
#pragma unroll
        for (int j = 0; j < 4; j++)
#pragma unroll
            for (int r = 0; r < 4; r++) acc[i][j][r] = 0.f;

    const int nch = K / 64;
    issue(0, 0); CP_COMMIT();

    for (int c = 0; c < nch; c++) {
        CP_WAIT0();
        __syncthreads();
        if (c + 1 < nch) { issue(c + 1, (c + 1) & 1); CP_COMMIT(); }

        const uint32_t bufb = sb + ((c & 1) * GEMM_BUF_W) * 4;

#pragma unroll
        for (int ks = 0; ks < 4; ks++) {
            uint32_t ah[2][4], bp[2][4];
#pragma unroll
            for (int mt = 0; mt < 2; mt++)
                ldsm4(ah[mt], bufb + aw + (mt * 16 * GS2 + ks * 8) * 4);
#pragma unroll
            for (int p = 0; p < 2; p++)
                ldsm4(bp[p], bufb + 4608 * 4 + bw + (p * 16 * GS2 + ks * 8) * 4);
#pragma unroll
            for (int mt = 0; mt < 2; mt++)
#pragma unroll
                for (int nt = 0; nt < 4; nt++)
                    mma_fp16(acc[mt][nt], ah[mt], &bp[nt >> 1][(nt & 1) * 2]);
        }
    }

#pragma unroll
    for (int mt = 0; mt < 2; mt++)
#pragma unroll
        for (int nt = 0; nt < 4; nt++) {
            int row = bm + wm * 32 + mt * 16 + (lane >> 2);
            int col = bn + wn * 32 + nt * 8 + 2 * (lane & 3);
            float v0 = acc[mt][nt][0], v1 = acc[mt][nt][1];
            float v2 = acc[mt][nt][2], v3 = acc[mt][nt][3];
            if (MODE == 1) {
                v0 = fmaxf(v0, 0.f); v1 = fmaxf(v1, 0.f);
                v2 = fmaxf(v2, 0.f); v3 = fmaxf(v3, 0.f);
                int wc = col >> 1;
                CP[(size_t)row * (N >> 1) + wc]       = pack2h(v0, v1);
                CP[(size_t)(row + 8) * (N >> 1) + wc] = pack2h(v2, v3);
            } else {
                *(float2*)&Cf[(size_t)row * N + col]       = make_float2(v0, v1);
                *(float2*)&Cf[(size_t)(row + 8) * N + col] = make_float2(v2, v3);
            }
        }
}

// ---------------------------------------------------------------------------
// Flash attention (128 threads, 64 q rows). qt = qt_base + reversed blockIdx.
// ---------------------------------------------------------------------------
#define AS 36
#define BUFW 4608
#define ATTN_SMEM (3 * BUFW * 4)

__global__ void __launch_bounds__(128)
attn_kernel(int qt_base) {
    extern __shared__ uint32_t sw[];
    const uint32_t sb = smem_u32(sw);

    const int t = threadIdx.x;
    const int lane = t & 31;
    const int wid = t >> 5;
    const int h = blockIdx.y;
    const int qt = qt_base + (int)gridDim.x - 1 - (int)blockIdx.x;
    const int qbase = qt * 64;
    const int hw0 = h * 32;

#pragma unroll
    for (int i = 0; i < 8; i++) {
        int idx = i * 128 + t;
        int row = idx >> 4;
        int w2  = (idx & 15) << 1;
        *(uint2*)&sw[row * AS + w2] =
            *(const uint2*)&g_QP[(size_t)(qbase + row) * KW + hw0 + w2];
    }
    __syncthreads();

    uint32_t qh[4][4];
    {
        uint32_t qa = sb + ((wid * 16 + (lane & 15)) * AS + (lane >> 4) * 4) * 4;
#pragma unroll
        for (int kc = 0; kc < 4; kc++)
            ldsm4(qh[kc], qa + kc * 32);
    }
    __syncthreads();

    const int g = lane >> 3;
    const uint32_t bw = (((g >> 1) * 8 + (lane & 7)) * AS + (g & 1) * 4) * 4;

    auto issueKV = [&](int kt, int b) {
        uint32_t dstb = sb + (b * BUFW) * 4;
        size_t krow = (size_t)kt * 64;
        size_t tb = ((size_t)(h * 64 + kt)) << 11;
#pragma unroll
        for (int j = 0; j < 4; j++) {
            int idx = j * 128 + t;
            int row = idx >> 3;
            int seg = (idx & 7) << 2;
            uint32_t d0 = dstb + (row * AS + seg) * 4;
            CP_ASYNC16(d0,            &g_KP[(krow + row) * KW + hw0 + seg]);
            CP_ASYNC16(d0 + 2304 * 4, &g_VP[tb + row * 32 + seg]);
        }
    };

    float o[8][4];
#pragma unroll
    for (int nt = 0; nt < 8; nt++)
#pragma unroll
        for (int r = 0; r < 4; r++) o[nt][r] = 0.f;
    float m0 = -1e30f, m1 = -1e30f, l0 = 0.f, l1 = 0.f;

    const uint32_t ones2[2] = {0x3C003C00u, 0x3C003C00u};

    issueKV(0, 0); CP_COMMIT();
    if (qt >= 1) { issueKV(1, 1); CP_COMMIT(); }

    for (int kt = 0; kt <= qt; kt++) {
        if (kt < qt) CP_WAIT1(); else CP_WAIT0();
        __syncthreads();
        if (kt + 2 <= qt) { issueKV(kt + 2, (kt + 2) % 3); CP_COMMIT(); }

        const uint32_t bufb = sb + ((kt % 3) * BUFW) * 4;

        float s[8][4];
#pragma unroll
        for (int nt = 0; nt < 8; nt++)
#pragma unroll
            for (int r = 0; r < 4; r++) s[nt][r] = 0.f;

#pragma unroll
        for (int kc = 0; kc < 4; kc++) {
            uint32_t kh4[4][4];
#pragma unroll
            for (int p = 0; p < 4; p++)
                ldsm4(kh4[p], bufb + bw + (p * 16 * AS + kc * 8) * 4);
#pragma unroll
            for (int nt = 0; nt < 8; nt++)
                mma_fp16(s[nt], qh[kc], &kh4[nt >> 1][(nt & 1) * 2]);
        }

        if (kt == qt) {
            int r0 = wid * 16 + (lane >> 2);
            int r1 = r0 + 8;
#pragma unroll
            for (int nt = 0; nt < 8; nt++) {
                int c0 = nt * 8 + 2 * (lane & 3);
                if (c0 > r0)     s[nt][0] = -1e30f;
                if (c0 + 1 > r0) s[nt][1] = -1e30f;
                if (c0 > r1)     s[nt][2] = -1e30f;
                if (c0 + 1 > r1) s[nt][3] = -1e30f;
            }
        }

        float rm0 = -1e30f, rm1 = -1e30f;
#pragma unroll
        for (int nt = 0; nt < 8; nt++) {
            rm0 = fmaxf(rm0, fmaxf(s[nt][0], s[nt][1]));
            rm1 = fmaxf(rm1, fmaxf(s[nt][2], s[nt][3]));
        }
        rm0 = fmaxf(rm0, __shfl_xor_sync(0xffffffffu, rm0, 1));
        rm0 = fmaxf(rm0, __shfl_xor_sync(0xffffffffu, rm0, 2));
        rm1 = fmaxf(rm1, __shfl_xor_sync(0xffffffffu, rm1, 1));
        rm1 = fmaxf(rm1, __shfl_xor_sync(0xffffffffu, rm1, 2));
        float mn0 = fmaxf(m0, rm0), mn1 = fmaxf(m1, rm1);
        float corr0 = ex2f(m0 - mn0), corr1 = ex2f(m1 - mn1);
        m0 = mn0; m1 = mn1;

        uint32_t ph[4][4];
#pragma unroll
        for (int nt = 0; nt < 8; nt++) {
            uint32_t p01 = ex2h2(pack2h(s[nt][0] - mn0, s[nt][1] - mn0));
            uint32_t p23 = ex2h2(pack2h(s[nt][2] - mn1, s[nt][3] - mn1));
            ph[nt >> 1][(nt & 1) * 2 + 0] = p01;
            ph[nt >> 1][(nt & 1) * 2 + 1] = p23;
        }

        float lacc[4] = {0.f, 0.f, 0.f, 0.f};
#pragma unroll
        for (int kc = 0; kc < 4; kc++)
            mma_fp16(lacc, ph[kc], ones2);
        l0 = l0 * corr0 + lacc[0];
        l1 = l1 * corr1 + lacc[2];

#pragma unroll
        for (int nt = 0; nt < 8; nt++) {
            o[nt][0] *= corr0; o[nt][1] *= corr0;
            o[nt][2] *= corr1; o[nt][3] *= corr1;
        }

#pragma unroll
        for (int kc = 0; kc < 4; kc++) {
            uint32_t vh4[4][4];
#pragma unroll
            for (int p = 0; p < 4; p++)
                ldsm4(vh4[p], bufb + 2304 * 4 + bw + (p * 16 * AS + kc * 8) * 4);
#pragma unroll
            for (int nt = 0; nt < 8; nt++)
                mma_fp16(o[nt], ph[kc], &vh4[nt >> 1][(nt & 1) * 2]);
        }
    }

    float inv0 = 1.f / l0, inv1 = 1.f / l1;
    int row = qbase + wid * 16 + (lane >> 2);
#pragma unroll
    for (int nt = 0; nt < 8; nt++) {
        int wc = hw0 + nt * 4 + (lane & 3);
        g_AtP[(size_t)row * KW + wc]       = pack2h(o[nt][0] * inv0, o[nt][1] * inv0);
        g_AtP[(size_t)(row + 8) * KW + wc] = pack2h(o[nt][2] * inv1, o[nt][3] * inv1);
    }
}

// ---------------------------------------------------------------------------
// LayerNorm
// ---------------------------------------------------------------------------
__global__ void ln_kernel(const float* __restrict__ in,
                          const float* __restrict__ gamma,
                          float* __restrict__ out) {
    __shared__ float sbuf[8];
    const int row = blockIdx.x;
    const int t   = threadIdx.x;

    float4 v = *(const float4*)&in[(size_t)row * DIM + (t << 2)];

    float s = v.x + v.y + v.z + v.w;
#pragma unroll
    for (int o = 16; o; o >>= 1) s += __shfl_xor_sync(0xffffffffu, s, o);
    if ((t & 31) == 0) sbuf[t >> 5] = s;
    __syncthreads();
    float tot = sbuf[0] + sbuf[1] + sbuf[2] + sbuf[3] +
                sbuf[4] + sbuf[5] + sbuf[6] + sbuf[7];
    float mean = tot * (1.f / (float)DIM);
    __syncthreads();

    float dx = v.x - mean, dy = v.y - mean, dz = v.z - mean, dw = v.w - mean;
    float s2 = dx * dx + dy * dy + dz * dz + dw * dw;
#pragma unroll
    for (int o = 16; o; o >>= 1) s2 += __shfl_xor_sync(0xffffffffu, s2, o);
    if ((t & 31) == 0) sbuf[t >> 5] = s2;
    __syncthreads();
    float tot2 = sbuf[0] + sbuf[1] + sbuf[2] + sbuf[3] +
                 sbuf[4] + sbuf[5] + sbuf[6] + sbuf[7];
    float rstd = rsqrtf(tot2 * (1.f / (float)DIM) + 1e-5f);

    float4 gm = *(const float4*)&gamma[t << 2];
    float4 r;
    r.x = dx * rstd * gm.x;
    r.y = dy * rstd * gm.y;
    r.z = dz * rstd * gm.z;
    r.w = dw * rstd * gm.w;
    *(float4*)&out[(size_t)row * DIM + (t << 2)] = r;
}

// ---------------------------------------------------------------------------
// launch: row-sliced attention/gemm1 overlap + off-path prep on side streams
// ---------------------------------------------------------------------------
extern "C" void kernel_launch(void* const* d_in, const int* in_sizes, int n_in,
                              void* d_out, int out_size) {
    const float* x     = (const float*)d_in[0];
    const float* Wqkv  = (const float*)d_in[1];
    const float* Wo1   = (const float*)d_in[2];
    const float* Wo2   = (const float*)d_in[3];
    const float* gamma = (const float*)d_in[4];
    float* out = (float*)d_out;

    float *qkv, *h2;
    uint32_t *XP, *AtP, *H1P, *WqkvP, *Wo1P, *Wo2P;
    cudaGetSymbolAddress((void**)&qkv, g_qkv);
    cudaGetSymbolAddress((void**)&h2, g_h2);
    cudaGetSymbolAddress((void**)&XP, g_XP);
    cudaGetSymbolAddress((void**)&AtP, g_AtP);
    cudaGetSymbolAddress((void**)&H1P, g_H1P);
    cudaGetSymbolAddress((void**)&WqkvP, g_WqkvP);
    cudaGetSymbolAddress((void**)&Wo1P, g_Wo1P);
    cudaGetSymbolAddress((void**)&Wo2P, g_Wo2P);

    static bool init_done = false;
    static cudaStream_t s2, s3;
    static cudaEvent_t ev_fork, ev_join, ev_hi, ev_g1hi;
    if (!init_done) {
        cudaFuncSetAttribute(attn_kernel,
                             cudaFuncAttributeMaxDynamicSharedMemorySize, ATTN_SMEM);
        cudaFuncSetAttribute(gemm_pre<0>,
                             cudaFuncAttributeMaxDynamicSharedMemorySize, GEMM_SMEM);
        cudaFuncSetAttribute(gemm_pre<1>,
                             cudaFuncAttributeMaxDynamicSharedMemorySize, GEMM_SMEM);
        cudaStreamCreateWithFlags(&s2, cudaStreamNonBlocking);
        cudaStreamCreateWithFlags(&s3, cudaStreamNonBlocking);
        cudaEventCreateWithFlags(&ev_fork, cudaEventDisableTiming);
        cudaEventCreateWithFlags(&ev_join, cudaEventDisableTiming);
        cudaEventCreateWithFlags(&ev_hi, cudaEventDisableTiming);
        cudaEventCreateWithFlags(&ev_g1hi, cudaEventDisableTiming);
        init_done = true;
    }

    // ---- fork: off-critical-path prep on s2 ----
    cudaEventRecord(ev_fork, 0);
    cudaStreamWaitEvent(s2, ev_fork, 0);
    trig_kernel<<<(N_TOK * 32) / 256, 256, 0, s2>>>();
    split_x_kernel<<<(N_TOK * KW) / 256, 256, 0, s2>>>(x);
    split_w_kernel<<<dim3(QKV_N / 64, DIM / 64, 2), 256, 0, s2>>>(
        Wqkv, Wo1, Wo2, 1);   // Wo1, Wo2
    cudaEventRecord(ev_join, s2);

    // ---- critical path ----
    split_w_kernel<<<dim3(QKV_N / 64, DIM / 64, 1), 256>>>(
        Wqkv, Wo1, Wo2, 0);   // Wqkv

    cudaStreamWaitEvent(0, ev_join, 0);   // need XP (and trig before rope)
    gemm_pre<0><<<dim3(QKV_N / 128, N_TOK / 128), 512, GEMM_SMEM>>>(
        XP, WqkvP, qkv, nullptr, N_TOK, QKV_N, DIM, 0);

    rope_v_kernel<<<dim3(64, HEADS), 256>>>();

    // attention hi-half (qt 32..63 = rows 2048..4095), then event
    attn_kernel<<<dim3(32, HEADS), 128, ATTN_SMEM>>>(32);
    cudaEventRecord(ev_hi, 0);

    // attention lo-half runs on default stream...
    attn_kernel<<<dim3(32, HEADS), 128, ATTN_SMEM>>>(0);

    // ...while gemm1 for hi rows overlaps on s3
    cudaStreamWaitEvent(s3, ev_hi, 0);
    gemm_pre<1><<<dim3(DIM / 128, (N_TOK / 2) / 128), 512, GEMM_SMEM, s3>>>(
        AtP, Wo1P, nullptr, H1P, N_TOK, DIM, DIM, 2048);
    cudaEventRecord(ev_g1hi, s3);

    // gemm1 lo rows on default stream (after attn_lo)
    gemm_pre<1><<<dim3(DIM / 128, (N_TOK / 2) / 128), 512, GEMM_SMEM>>>(
        AtP, Wo1P, nullptr, H1P, N_TOK, DIM, DIM, 0);

    // join: gemm2 needs full H1P
    cudaStreamWaitEvent(0, ev_g1hi, 0);
    gemm_pre<0><<<dim3(DIM / 128, N_TOK / 128), 512, GEMM_SMEM>>>(
        H1P, Wo2P, h2, nullptr, N_TOK, DIM, DIM, 0);

    ln_kernel<<<N_TOK, 256>>>(h2, gamma, out);
}

// round 15
// speedup vs baseline: 1.0542x; 1.0542x over previous
#include <cuda_runtime.h>
#include <cuda_bf16.h>
#include <cuda_fp16.h>
#include <math.h>
#include <stdint.h>

#define N_TOK   4096
#define DIM     1024
#define HEADS   16
#define HD      64
#define QKV_N   3072
#define KW      (DIM / 2)

#define QSCALE  0.180336880111120429f

// ---------------------------------------------------------------------------
// Scratch
// ---------------------------------------------------------------------------
__device__ float    g_qkv[N_TOK * QKV_N];
__device__ float    g_h2[N_TOK * DIM];
__device__ float4   g_trig[N_TOK * 32];
__device__ uint32_t g_XP[N_TOK * KW];
__device__ uint32_t g_QP[N_TOK * KW];
__device__ uint32_t g_KP[N_TOK * KW];
__device__ uint32_t g_VP[HEADS * 64 * 2048];
__device__ uint32_t g_AtP[N_TOK * KW];
__device__ uint32_t g_H1P[N_TOK * KW];
__device__ uint32_t g_WqkvP[QKV_N * KW];
__device__ uint32_t g_Wo1P[DIM * KW];
__device__ uint32_t g_Wo2P[DIM * KW];

// ---------------------------------------------------------------------------
// helpers
// ---------------------------------------------------------------------------
__device__ __forceinline__ uint32_t pack2h(float lo, float hi) {
    uint32_t r;
    asm("cvt.rn.f16x2.f32 %0, %1, %2;" : "=r"(r) : "f"(hi), "f"(lo));
    return r;
}
__device__ __forceinline__ float ex2f(float x) {
    float r;
    asm("ex2.approx.f32 %0, %1;" : "=f"(r) : "f"(x));
    return r;
}
__device__ __forceinline__ uint32_t ex2h2(uint32_t x) {
    uint32_t r;
    asm("ex2.approx.f16x2 %0, %1;" : "=r"(r) : "r"(x));
    return r;
}
__device__ __forceinline__ void mma_fp16(float* c, const uint32_t* a, const uint32_t* b) {
    asm volatile("mma.sync.aligned.m16n8k16.row.col.f32.f16.f16.f32 "
        "{%0,%1,%2,%3}, {%4,%5,%6,%7}, {%8,%9}, {%0,%1,%2,%3};"
        : "+f"(c[0]), "+f"(c[1]), "+f"(c[2]), "+f"(c[3])
        : "r"(a[0]), "r"(a[1]), "r"(a[2]), "r"(a[3]), "r"(b[0]), "r"(b[1]));
}
__device__ __forceinline__ void ldsm4(uint32_t* r, uint32_t addr) {
    asm volatile("ldmatrix.sync.aligned.m8n8.x4.shared.b16 {%0,%1,%2,%3}, [%4];"
        : "=r"(r[0]), "=r"(r[1]), "=r"(r[2]), "=r"(r[3]) : "r"(addr));
}
__device__ __forceinline__ uint32_t smem_u32(const void* p) {
    uint32_t a;
    asm("{ .reg .u64 t; cvta.to.shared.u64 t, %1; cvt.u32.u64 %0, t; }"
        : "=r"(a) : "l"(p));
    return a;
}
#define CP_ASYNC16(dst, src) \
    asm volatile("cp.async.cg.shared.global [%0], [%1], 16;" :: "r"(dst), "l"(src))
#define CP_COMMIT() asm volatile("cp.async.commit_group;")
#define CP_WAIT0()  asm volatile("cp.async.wait_group 0;")
#define CP_WAIT1()  asm volatile("cp.async.wait_group 1;")

// ---------------------------------------------------------------------------
// Unified prep kernel: all independent prep work in ONE launch.
// Block ranges:
//   [0, 8192)      split_x     (idx = b*256+t over N_TOK*KW)
//   [8192, 8704)   trig table  (idx over N_TOK*32)
//   [8704, 9472)   Wqkv split  (768 = 48 n-blocks x 16 k-blocks)
//   [9472, 9728)   Wo1 split   (256 = 16 x 16)
//   [9728, 9984)   Wo2 split
// ---------------------------------------------------------------------------
#define PREP_BLOCKS 9984

__global__ void prep_kernel(const float* __restrict__ x,
                            const float* __restrict__ W0,
                            const float* __restrict__ W1,
                            const float* __restrict__ W2) {
    __shared__ float S[64][68];
    const int b = blockIdx.x;
    const int t = threadIdx.x;

    if (b < 8192) {
        int idx = b * 256 + t;
        float2 v = *(const float2*)&x[(size_t)idx * 2];
        g_XP[idx] = pack2h(v.x, v.y);
        return;
    }
    if (b < 8704) {
        int idx = (b - 8192) * 256 + t;
        int row = idx >> 5;
        int w   = idx & 31;
        int d0  = w * 2;
        int i0  = d0 & 31;
        float invf0 = powf(10000.f, -(float)i0 * (1.f / 32.f));
        float invf1 = powf(10000.f, -(float)(i0 + 1) * (1.f / 32.f));
        float4 r;
        sincosf((float)row * invf0, &r.x, &r.y);
        sincosf((float)row * invf1, &r.z, &r.w);
        g_trig[idx] = r;
        return;
    }

    const float* W;
    uint32_t* P;
    int N, n0, k0;
    if (b < 9472) {
        int i2 = b - 8704;
        W = W0; P = g_WqkvP; N = QKV_N;
        n0 = (i2 % 48) * 64; k0 = (i2 / 48) * 64;
    } else if (b < 9728) {
        int i2 = b - 9472;
        W = W1; P = g_Wo1P; N = DIM;
        n0 = (i2 & 15) * 64; k0 = (i2 >> 4) * 64;
    } else {
        int i2 = b - 9728;
        W = W2; P = g_Wo2P; N = DIM;
        n0 = (i2 & 15) * 64; k0 = (i2 >> 4) * 64;
    }

#pragma unroll
    for (int i = 0; i < 4; i++) {
        int slot = i * 256 + t;
        int k = slot >> 4, n4 = (slot & 15) << 2;
        *(float4*)&S[k][n4] = *(const float4*)&W[(size_t)(k0 + k) * N + n0 + n4];
    }
    __syncthreads();
#pragma unroll
    for (int i = 0; i < 8; i++) {
        int slot = i * 256 + t;
        int n = slot >> 5, kwl = slot & 31;
        P[(size_t)(n0 + n) * KW + (k0 >> 1) + kwl] = pack2h(S[2 * kwl][n], S[2 * kwl + 1][n]);
    }
}

// ---------------------------------------------------------------------------
// RoPE (table-driven) + V transpose-pack, one block per (kv-tile, head).
// ---------------------------------------------------------------------------
__global__ void rope_v_kernel() {
    __shared__ float S[64][68];
    const int t = threadIdx.x;
    const int kt = blockIdx.x, h = blockIdx.y;

#pragma unroll
    for (int i = 0; i < 4; i++) {
        int slot = i * 256 + t;
        int r = slot >> 4, c4 = (slot & 15) << 2;
        *(float4*)&S[r][c4] =
            *(const float4*)&g_qkv[(size_t)(kt * 64 + r) * QKV_N + 2 * DIM + h * HD + c4];
    }
    __syncthreads();
    size_t tb = ((size_t)(h * 64 + kt)) << 11;
#pragma unroll
    for (int i = 0; i < 8; i++) {
        int slot = i * 256 + t;
        int d = slot >> 5, p = slot & 31;
        g_VP[tb + slot] = pack2h(S[2 * p][d], S[2 * p + 1][d]);
    }

#pragma unroll
    for (int i = 0; i < 8; i++) {
        int slot = i * 256 + t;
        int r = slot >> 5, w = slot & 31;
        int row = kt * 64 + r;
        int d0 = w * 2;

        float4 tr = g_trig[row * 32 + w];
        float s0 = tr.x, c0 = tr.y, s1 = tr.z, c1 = tr.w;

        bool half = (d0 < 32);
        size_t base = (size_t)row * QKV_N + h * HD + d0;
        size_t pb   = half ? base + 32 : base - 32;

        float q0 = g_qkv[base],       q1 = g_qkv[base + 1];
        float qp0 = g_qkv[pb],        qp1 = g_qkv[pb + 1];
        float k0 = g_qkv[base + DIM], k1 = g_qkv[base + DIM + 1];
        float kp0 = g_qkv[pb + DIM],  kp1 = g_qkv[pb + DIM + 1];

        float oq0, oq1, ok0, ok1;
        if (half) {
            oq0 = q0 * c0 - qp0 * s0;  oq1 = q1 * c1 - qp1 * s1;
            ok0 = k0 * c0 - kp0 * s0;  ok1 = k1 * c1 - kp1 * s1;
        } else {
            oq0 = q0 * c0 + qp0 * s0;  oq1 = q1 * c1 + qp1 * s1;
            ok0 = k0 * c0 + kp0 * s0;  ok1 = k1 * c1 + kp1 * s1;
        }
        oq0 *= QSCALE; oq1 *= QSCALE;

        size_t widx = (size_t)row * KW + h * 32 + w;
        g_QP[widx] = pack2h(oq0, oq1);
        g_KP[widx] = pack2h(ok0, ok1);
    }
}

// ---------------------------------------------------------------------------
// GEMM: single fp16 A x single fp16 B, BK=64, 2-stage cp.async.
// ---------------------------------------------------------------------------
#define GS2 36
#define GEMM_BUF_W (2 * 128 * GS2)
#define GEMM_SMEM  (2 * GEMM_BUF_W * 4)

template <int MODE>
__global__ void __launch_bounds__(512)
gemm_pre(const uint32_t* __restrict__ AP, const uint32_t* __restrict__ BP,
         float* __restrict__ Cf, uint32_t* __restrict__ CP,
         int M, int N, int K) {
    extern __shared__ uint32_t sw[];
    const int kw = K >> 1;
    const int t = threadIdx.x;
    const int lane = t & 31;
    const int wid = t >> 5;
    const int wm = wid & 3;
    const int wn = wid >> 2;
    const int bm = blockIdx.y * 128;
    const int bn = blockIdx.x * 128;
    const uint32_t sb = smem_u32(sw);

    const int frow = t >> 2;
    const int fw0  = (t & 3) << 3;
    const uint32_t* sAP = &AP[(size_t)(bm + frow) * kw + fw0];
    const uint32_t* sBP = &BP[(size_t)(bn + frow) * kw + fw0];
    const uint32_t dbase = sb + (frow * GS2 + fw0) * 4;

    auto issue = [&](int c, int b) {
        uint32_t d = dbase + (b * GEMM_BUF_W) * 4;
        int go = c * 32;
        CP_ASYNC16(d,                  sAP + go);
        CP_ASYNC16(d + 16,             sAP + go + 4);
        CP_ASYNC16(d + 4608 * 4,       sBP + go);
        CP_ASYNC16(d + 4608 * 4 + 16,  sBP + go + 4);
    };

    const uint32_t aw = ((wm * 32 + (lane & 15)) * GS2 + (lane >> 4) * 4) * 4;
    const int g = lane >> 3;
    const uint32_t bw = ((wn * 32 + (g >> 1) * 8 + (lane & 7)) * GS2 + (g & 1) * 4) * 4;

    float acc[2][4][4];
#pragma unroll
    for (int i = 0; i < 2; i++)
#pragma unroll
        for (int j = 0; j < 4; j++)
#pragma unroll
            for (int r = 0; r < 4; r++) acc[i][j][r] = 0.f;

    const int nch = K / 64;
    issue(0, 0); CP_COMMIT();

    for (int c = 0; c < nch; c++) {
        CP_WAIT0();
        __syncthreads();
        if (c + 1 < nch) { issue(c + 1, (c + 1) & 1); CP_COMMIT(); }

        const uint32_t bufb = sb + ((c & 1) * GEMM_BUF_W) * 4;

#pragma unroll
        for (int ks = 0; ks < 4; ks++) {
            uint32_t ah[2][4], bp[2][4];
#pragma unroll
            for (int mt = 0; mt < 2; mt++)
                ldsm4(ah[mt], bufb + aw + (mt * 16 * GS2 + ks * 8) * 4);
#pragma unroll
            for (int p = 0; p < 2; p++)
                ldsm4(bp[p], bufb + 4608 * 4 + bw + (p * 16 * GS2 + ks * 8) * 4);
#pragma unroll
            for (int mt = 0; mt < 2; mt++)
#pragma unroll
                for (int nt = 0; nt < 4; nt++)
                    mma_fp16(acc[mt][nt], ah[mt], &bp[nt >> 1][(nt & 1) * 2]);
        }
    }

#pragma unroll
    for (int mt = 0; mt < 2; mt++)
#pragma unroll
        for (int nt = 0; nt < 4; nt++) {
            int row = bm + wm * 32 + mt * 16 + (lane >> 2);
            int col = bn + wn * 32 + nt * 8 + 2 * (lane & 3);
            float v0 = acc[mt][nt][0], v1 = acc[mt][nt][1];
            float v2 = acc[mt][nt][2], v3 = acc[mt][nt][3];
            if (MODE == 1) {
                v0 = fmaxf(v0, 0.f); v1 = fmaxf(v1, 0.f);
                v2 = fmaxf(v2, 0.f); v3 = fmaxf(v3, 0.f);
                int wc = col >> 1;
                CP[(size_t)row * (N >> 1) + wc]       = pack2h(v0, v1);
                CP[(size_t)(row + 8) * (N >> 1) + wc] = pack2h(v2, v3);
            } else {
                *(float2*)&Cf[(size_t)row * N + col]       = make_float2(v0, v1);
                *(float2*)&Cf[(size_t)(row + 8) * N + col] = make_float2(v2, v3);
            }
        }
}

// ---------------------------------------------------------------------------
// Flash attention (128 threads, 64 q rows, log2-domain softmax).
// ---------------------------------------------------------------------------
#define AS 36
#define BUFW 4608
#define ATTN_SMEM (3 * BUFW * 4)

__global__ void __launch_bounds__(128)
attn_kernel() {
    extern __shared__ uint32_t sw[];
    const uint32_t sb = smem_u32(sw);

    const int t = threadIdx.x;
    const int lane = t & 31;
    const int wid = t >> 5;
    const int h = blockIdx.y;
    const int qt = (int)gridDim.x - 1 - (int)blockIdx.x;
    const int qbase = qt * 64;
    const int hw0 = h * 32;

#pragma unroll
    for (int i = 0; i < 8; i++) {
        int idx = i * 128 + t;
        int row = idx >> 4;
        int w2  = (idx & 15) << 1;
        *(uint2*)&sw[row * AS + w2] =
            *(const uint2*)&g_QP[(size_t)(qbase + row) * KW + hw0 + w2];
    }
    __syncthreads();

    uint32_t qh[4][4];
    {
        uint32_t qa = sb + ((wid * 16 + (lane & 15)) * AS + (lane >> 4) * 4) * 4;
#pragma unroll
        for (int kc = 0; kc < 4; kc++)
            ldsm4(qh[kc], qa + kc * 32);
    }
    __syncthreads();

    const int g = lane >> 3;
    const uint32_t bw = (((g >> 1) * 8 + (lane & 7)) * AS + (g & 1) * 4) * 4;

    auto issueKV = [&](int kt, int b) {
        uint32_t dstb = sb + (b * BUFW) * 4;
        size_t krow = (size_t)kt * 64;
        size_t tb = ((size_t)(h * 64 + kt)) << 11;
#pragma unroll
        for (int j = 0; j < 4; j++) {
            int idx = j * 128 + t;
            int row = idx >> 3;
            int seg = (idx & 7) << 2;
            uint32_t d0 = dstb + (row * AS + seg) * 4;
            CP_ASYNC16(d0,            &g_KP[(krow + row) * KW + hw0 + seg]);
            CP_ASYNC16(d0 + 2304 * 4, &g_VP[tb + row * 32 + seg]);
        }
    };

    float o[8][4];
#pragma unroll
    for (int nt = 0; nt < 8; nt++)
#pragma unroll
        for (int r = 0; r < 4; r++) o[nt][r] = 0.f;
    float m0 = -1e30f, m1 = -1e30f, l0 = 0.f, l1 = 0.f;

    const uint32_t ones2[2] = {0x3C003C00u, 0x3C003C00u};

    issueKV(0, 0); CP_COMMIT();
    if (qt >= 1) { issueKV(1, 1); CP_COMMIT(); }

    for (int kt = 0; kt <= qt; kt++) {
        if (kt < qt) CP_WAIT1(); else CP_WAIT0();
        __syncthreads();
        if (kt + 2 <= qt) { issueKV(kt + 2, (kt + 2) % 3); CP_COMMIT(); }

        const uint32_t bufb = sb + ((kt % 3) * BUFW) * 4;

        float s[8][4];
#pragma unroll
        for (int nt = 0; nt < 8; nt++)
#pragma unroll
            for (int r = 0; r < 4; r++) s[nt][r] = 0.f;

#pragma unroll
        for (int kc = 0; kc < 4; kc++) {
            uint32_t kh4[4][4];
#pragma unroll
            for (int p = 0; p < 4; p++)
                ldsm4(kh4[p], bufb + bw + (p * 16 * AS + kc * 8) * 4);
#pragma unroll
            for (int nt = 0; nt < 8; nt++)
                mma_fp16(s[nt], qh[kc], &kh4[nt >> 1][(nt & 1) * 2]);
        }

        if (kt == qt) {
            int r0 = wid * 16 + (lane >> 2);
            int r1 = r0 + 8;
#pragma unroll
            for (int nt = 0; nt < 8; nt++) {
                int c0 = nt * 8 + 2 * (lane & 3);
                if (c0 > r0)     s[nt][0] = -1e30f;
                if (c0 + 1 > r0) s[nt][1] = -1e30f;
                if (c0 > r1)     s[nt][2] = -1e30f;
                if (c0 + 1 > r1) s[nt][3] = -1e30f;
            }
        }

        float rm0 = -1e30f, rm1 = -1e30f;
#pragma unroll
        for (int nt = 0; nt < 8; nt++) {
            rm0 = fmaxf(rm0, fmaxf(s[nt][0], s[nt][1]));
            rm1 = fmaxf(rm1, fmaxf(s[nt][2], s[nt][3]));
        }
        rm0 = fmaxf(rm0, __shfl_xor_sync(0xffffffffu, rm0, 1));
        rm0 = fmaxf(rm0, __shfl_xor_sync(0xffffffffu, rm0, 2));
        rm1 = fmaxf(rm1, __shfl_xor_sync(0xffffffffu, rm1, 1));
        rm1 = fmaxf(rm1, __shfl_xor_sync(0xffffffffu, rm1, 2));
        float mn0 = fmaxf(m0, rm0), mn1 = fmaxf(m1, rm1);
        float corr0 = ex2f(m0 - mn0), corr1 = ex2f(m1 - mn1);
        m0 = mn0; m1 = mn1;

        uint32_t ph[4][4];
#pragma unroll
        for (int nt = 0; nt < 8; nt++) {
            uint32_t p01 = ex2h2(pack2h(s[nt][0] - mn0, s[nt][1] - mn0));
            uint32_t p23 = ex2h2(pack2h(s[nt][2] - mn1, s[nt][3] - mn1));
            ph[nt >> 1][(nt & 1) * 2 + 0] = p01;
            ph[nt >> 1][(nt & 1) * 2 + 1] = p23;
        }

        float lacc[4] = {0.f, 0.f, 0.f, 0.f};
#pragma unroll
        for (int kc = 0; kc < 4; kc++)
            mma_fp16(lacc, ph[kc], ones2);
        l0 = l0 * corr0 + lacc[0];
        l1 = l1 * corr1 + lacc[2];

#pragma unroll
        for (int nt = 0; nt < 8; nt++) {
            o[nt][0] *= corr0; o[nt][1] *= corr0;
            o[nt][2] *= corr1; o[nt][3] *= corr1;
        }

#pragma unroll
        for (int kc = 0; kc < 4; kc++) {
            uint32_t vh4[4][4];
#pragma unroll
            for (int p = 0; p < 4; p++)
                ldsm4(vh4[p], bufb + 2304 * 4 + bw + (p * 16 * AS + kc * 8) * 4);
#pragma unroll
            for (int nt = 0; nt < 8; nt++)
                mma_fp16(o[nt], ph[kc], &vh4[nt >> 1][(nt & 1) * 2]);
        }
    }

    float inv0 = 1.f / l0, inv1 = 1.f / l1;
    int row = qbase + wid * 16 + (lane >> 2);
#pragma unroll
    for (int nt = 0; nt < 8; nt++) {
        int wc = hw0 + nt * 4 + (lane & 3);
        g_AtP[(size_t)row * KW + wc]       = pack2h(o[nt][0] * inv0, o[nt][1] * inv0);
        g_AtP[(size_t)(row + 8) * KW + wc] = pack2h(o[nt][2] * inv1, o[nt][3] * inv1);
    }
}

// ---------------------------------------------------------------------------
// LayerNorm
// ---------------------------------------------------------------------------
__global__ void ln_kernel(const float* __restrict__ in,
                          const float* __restrict__ gamma,
                          float* __restrict__ out) {
    __shared__ float sbuf[8];
    const int row = blockIdx.x;
    const int t   = threadIdx.x;

    float4 v = *(const float4*)&in[(size_t)row * DIM + (t << 2)];

    float s = v.x + v.y + v.z + v.w;
#pragma unroll
    for (int o = 16; o; o >>= 1) s += __shfl_xor_sync(0xffffffffu, s, o);
    if ((t & 31) == 0) sbuf[t >> 5] = s;
    __syncthreads();
    float tot = sbuf[0] + sbuf[1] + sbuf[2] + sbuf[3] +
                sbuf[4] + sbuf[5] + sbuf[6] + sbuf[7];
    float mean = tot * (1.f / (float)DIM);
    __syncthreads();

    float dx = v.x - mean, dy = v.y - mean, dz = v.z - mean, dw = v.w - mean;
    float s2 = dx * dx + dy * dy + dz * dz + dw * dw;
#pragma unroll
    for (int o = 16; o; o >>= 1) s2 += __shfl_xor_sync(0xffffffffu, s2, o);
    if ((t & 31) == 0) sbuf[t >> 5] = s2;
    __syncthreads();
    float tot2 = sbuf[0] + sbuf[1] + sbuf[2] + sbuf[3] +
                 sbuf[4] + sbuf[5] + sbuf[6] + sbuf[7];
    float rstd = rsqrtf(tot2 * (1.f / (float)DIM) + 1e-5f);

    float4 gm = *(const float4*)&gamma[t << 2];
    float4 r;
    r.x = dx * rstd * gm.x;
    r.y = dy * rstd * gm.y;
    r.z = dz * rstd * gm.z;
    r.w = dw * rstd * gm.w;
    *(float4*)&out[(size_t)row * DIM + (t << 2)] = r;
}

// ---------------------------------------------------------------------------
// launch (serial, R12 structure + unified prep)
// ---------------------------------------------------------------------------
extern "C" void kernel_launch(void* const* d_in, const int* in_sizes, int n_in,
                              void* d_out, int out_size) {
    const float* x     = (const float*)d_in[0];
    const float* Wqkv  = (const float*)d_in[1];
    const float* Wo1   = (const float*)d_in[2];
    const float* Wo2   = (const float*)d_in[3];
    const float* gamma = (const float*)d_in[4];
    float* out = (float*)d_out;

    float *qkv, *h2;
    uint32_t *XP, *AtP, *H1P, *WqkvP, *Wo1P, *Wo2P;
    cudaGetSymbolAddress((void**)&qkv, g_qkv);
    cudaGetSymbolAddress((void**)&h2, g_h2);
    cudaGetSymbolAddress((void**)&XP, g_XP);
    cudaGetSymbolAddress((void**)&AtP, g_AtP);
    cudaGetSymbolAddress((void**)&H1P, g_H1P);
    cudaGetSymbolAddress((void**)&WqkvP, g_WqkvP);
    cudaGetSymbolAddress((void**)&Wo1P, g_Wo1P);
    cudaGetSymbolAddress((void**)&Wo2P, g_Wo2P);

    static bool init_done = false;
    if (!init_done) {
        cudaFuncSetAttribute(attn_kernel,
                             cudaFuncAttributeMaxDynamicSharedMemorySize, ATTN_SMEM);
        cudaFuncSetAttribute(gemm_pre<0>,
                             cudaFuncAttributeMaxDynamicSharedMemorySize, GEMM_SMEM);
        cudaFuncSetAttribute(gemm_pre<1>,
                             cudaFuncAttributeMaxDynamicSharedMemorySize, GEMM_SMEM);
        init_done = true;
    }

    // unified prep: x split + trig table + all three weight splits
    prep_kernel<<<PREP_BLOCKS, 256>>>(x, Wqkv, Wo1, Wo2);

    gemm_pre<0><<<dim3(QKV_N / 128, N_TOK / 128), 512, GEMM_SMEM>>>(
        XP, WqkvP, qkv, nullptr, N_TOK, QKV_N, DIM);

    rope_v_kernel<<<dim3(64, HEADS), 256>>>();

    attn_kernel<<<dim3(64, HEADS), 128, ATTN_SMEM>>>();

    gemm_pre<1><<<dim3(DIM / 128, N_TOK / 128), 512, GEMM_SMEM>>>(
        AtP, Wo1P, nullptr, H1P, N_TOK, DIM, DIM);

    gemm_pre<0><<<dim3(DIM / 128, N_TOK / 128), 512, GEMM_SMEM>>>(
        H1P, Wo2P, h2, nullptr, N_TOK, DIM, DIM);

    ln_kernel<<<N_TOK, 256>>>(h2, gamma, out);
}